// round 11
// baseline (speedup 1.0000x reference)
#include <cuda_runtime.h>

#define NN 256
#define CC 64
#define TT 64
#define VV 25
#define SS 3
#define RR 8
#define OO 64
#define HH 16
#define KK 75   // S*V contraction length

// ---- scratch ----
__device__ float g_xm[NN * CC * VV];
__device__ float g_m[NN * SS * OO * VV * VV];            // [n][s][o][v][u]
__device__ float g_x3[(size_t)NN * OO * KK * TT];        // [n][o][k][t]
__device__ float g_y[NN * OO * TT * VV];                 // [n][o][t][u]
__device__ float g_pool[NN * OO];                        // raw sums of y per (n,o)
__device__ float g_sea[NN * OO];
__device__ float g_seb[NN * OO];

// ============================================================
// K0: dummy (keeps k3a at the profiler's captured launch index)
// ============================================================
__global__ void k0_dummy() {}

// ============================================================
// K1: xm[n,c,v] = mean over T
// ============================================================
__global__ void k1_mean(const float* __restrict__ x) {
    int idx = blockIdx.x * 256 + threadIdx.x;
    if (idx >= NN * CC * VV) return;
    int v  = idx % VV;
    int nc = idx / VV;
    const float* p = x + (size_t)nc * (TT * VV) + v;
    float s = 0.f;
#pragma unroll
    for (int t = 0; t < TT; ++t) s += p[t * VV];
    g_xm[idx] = s * (1.0f / TT);
}

// ============================================================
// K2: attention map + softmax. CTA per (n,s), 256 threads.
// ============================================================
__global__ void k2_attn(const float* __restrict__ PA, const float* __restrict__ alpha,
                        const float* __restrict__ w1, const float* __restrict__ b1,
                        const float* __restrict__ w2, const float* __restrict__ b2,
                        const float* __restrict__ w4, const float* __restrict__ b4) {
    int n = blockIdx.x / SS, s = blockIdx.x % SS;
    int tid = threadIdx.x;

    __shared__ float xms[CC * VV];
    __shared__ float x1s[RR * VV];
    __shared__ float x2s[RR * VV];
    __shared__ float atts[RR * VV * VV];

    for (int i = tid; i < CC * VV; i += 256) xms[i] = g_xm[n * CC * VV + i];
    __syncthreads();

    for (int i2 = tid; i2 < 2 * RR * VV; i2 += 256) {
        int which = i2 / (RR * VV);
        int i = i2 % (RR * VV);
        int r = i / VV, u = i % VV;
        const float* w = (which ? w2 : w1) + (s * RR + r) * CC;
        float acc = (which ? b2 : b1)[s * RR + r];
#pragma unroll
        for (int c = 0; c < CC; ++c) acc += w[c] * xms[c * VV + u];
        (which ? x2s : x1s)[i] = acc;
    }
    __syncthreads();

    for (int i = tid; i < RR * VV * VV; i += 256) {
        int r = i / (VV * VV); int rem = i % (VV * VV);
        int u = rem / VV, v = rem % VV;
        atts[i] = tanhf(x1s[r * VV + u] - x2s[r * VV + v]);
    }
    __syncthreads();

    float al = alpha[s];
    for (int pos = tid; pos < OO * VV; pos += 256) {
        int o = pos / VV, v = pos % VV;
        float wr[RR];
#pragma unroll
        for (int r = 0; r < RR; ++r) wr[r] = w4[(s * OO + o) * RR + r];
        float b4v = b4[s * OO + o];
        float col[VV];
        float mx = -1e30f;
#pragma unroll
        for (int u = 0; u < VV; ++u) {
            float acc = b4v;
#pragma unroll
            for (int r = 0; r < RR; ++r) acc += wr[r] * atts[r * VV * VV + u * VV + v];
            float val = al * acc + PA[(s * VV + u) * VV + v] + PA[(s * VV + v) * VV + u];
            col[u] = val;
            mx = fmaxf(mx, val);
        }
        float ssum = 0.f;
#pragma unroll
        for (int u = 0; u < VV; ++u) { col[u] = __expf(col[u] - mx); ssum += col[u]; }
        float inv = 1.0f / ssum;
        float* outp = g_m + (((size_t)(n * SS + s) * OO + o) * VV + v) * VV;
#pragma unroll
        for (int u = 0; u < VV; ++u) outp[u] = col[u] * inv;
    }
}

// ============================================================
// K3a: x3[n,o,s*25+v,t] = b3[s,o] + sum_c w3[s,o,c] x[n,c,t,v]
// CTA = (n, s, t-chunk of 4). 256 threads = (o-pair:32, t:8 -> here t:4 x2).
// R8 proven structure, TCH=4: 45.3KB smem -> 3 CTAs/SM at natural regs.
// Thread layout: 32 o-pairs x (t in 0..3), 2 threads per (o-pair,t)? No —
// keep (o-pair:32) x (t:8) shape but TCH=4 means t index is tid&3 and the
// upper bit widens o coverage: use 64 o-pairs? O=64 -> 32 pairs. So use
// 256 = 32 pairs x 8, with t = (tid&7) mapping 2 threads per t? Instead:
// 256 threads = (o-pair:64? no). Simplest: 32 pairs x 4 t = 128 threads
// doing compute twice (two o-pair groups): split o-pairs across tid>>2.
// Layout: tid = opair*4 + t, opair in 0..63 -> covers o in steps of 1 pair
// but only 32 pairs exist... Use 256 threads = (opair:32, t:4, dup:2) where
// dup splits the c-sum? Simpler: 256 threads = opair(32) x t(4) x half(2),
// each half handles 32 of the 64 c-channels, atomically combined in smem?
// No atomics needed: halves write partial sums to smem and one half adds.
// -- To keep it SIMPLE and proven: 128 active compute threads (opair x t),
// all 256 stage. Compute work per thread doubles vs R8 but CTAs/SM = 3.
// ============================================================
#define TCH 4
#define XSP 28
__global__ void __launch_bounds__(256)
k3a_x3(const float* __restrict__ x, const float* __restrict__ w3,
       const float* __restrict__ b3) {
    int bid = blockIdx.x;
    int n = bid / (SS * (TT / TCH));
    int rem = bid % (SS * (TT / TCH));
    int s = rem / (TT / TCH);
    int t0 = (rem % (TT / TCH)) * TCH;
    int tid = threadIdx.x;
    // 256 threads = 64 o-groups x 4 t ; each thread handles ONE o (not pair)
    // but shares x loads across the 4 t?? -> Revert to exact R8 inner shape:
    // o-pair x t, with 32 pairs x 4 t = 128 threads for o in [0,64) as pairs
    // and the other 128 threads take o-pairs 32..63?? O=64 -> exactly 32
    // pairs. So: tid<128 computes; everyone stages.  (work/thread == R8)
    int cp = tid >> 2;            // 0..63 : o-pair id over TWO t-chunks
    int opair = cp & 31;          // 0..31
    int tg = cp >> 5;             // 0..1 : which t-subchunk? No—TCH=4 only.
    // Final simple mapping: 256 threads = (opair:32) x (t:4) x (csel:2).
    // csel splits the c loop in half; partials combined via smem.
    int o0 = opair * 2;
    int t = (tid >> 1) & 3;
    int csel = tid & 1;
    (void)tg;

    __shared__ float w3s[OO * 65];            // 16.6KB
    __shared__ float x_s[CC * TCH * XSP];     // 28.7KB
    __shared__ float partial[256];            // 1KB (for csel combine)

    // fix thread mapping derived values
    o0 = ((tid >> 3) & 31) * 2;   // 32 o-pairs from bits [3..7]
    t = tid & 3;                  // 4 t
    csel = (tid >> 2) & 1;        // c half

    for (int i = tid; i < OO * CC; i += 256) {
        int oo2 = i >> 6, c = i & 63;
        w3s[oo2 * 65 + c] = w3[s * OO * CC + i];
    }
    for (int j = tid; j < CC * TCH * VV; j += 256) {
        int c = j / (TCH * VV);
        int tv = j % (TCH * VV);
        int tl = tv / VV, v = tv % VV;
        x_s[c * (TCH * XSP) + tl * XSP + v] =
            x[((size_t)(n * CC + c) * TT + (t0 + tl)) * VV + v];
    }
    __syncthreads();

    float acc0[VV], acc1[VV];
#pragma unroll
    for (int v = 0; v < VV; ++v) { acc0[v] = 0.f; acc1[v] = 0.f; }

    int cbase = csel * 32;
#pragma unroll 2
    for (int ci = 0; ci < 32; ++ci) {
        int c = cbase + ci;
        float wv0 = w3s[o0 * 65 + c];
        float wv1 = w3s[(o0 + 1) * 65 + c];
        const float* xr = x_s + c * (TCH * XSP) + t * XSP;
#pragma unroll
        for (int v4 = 0; v4 < 6; ++v4) {
            float4 q = *(const float4*)(xr + v4 * 4);
            acc0[v4 * 4 + 0] = fmaf(wv0, q.x, acc0[v4 * 4 + 0]);
            acc0[v4 * 4 + 1] = fmaf(wv0, q.y, acc0[v4 * 4 + 1]);
            acc0[v4 * 4 + 2] = fmaf(wv0, q.z, acc0[v4 * 4 + 2]);
            acc0[v4 * 4 + 3] = fmaf(wv0, q.w, acc0[v4 * 4 + 3]);
            acc1[v4 * 4 + 0] = fmaf(wv1, q.x, acc1[v4 * 4 + 0]);
            acc1[v4 * 4 + 1] = fmaf(wv1, q.y, acc1[v4 * 4 + 1]);
            acc1[v4 * 4 + 2] = fmaf(wv1, q.z, acc1[v4 * 4 + 2]);
            acc1[v4 * 4 + 3] = fmaf(wv1, q.w, acc1[v4 * 4 + 3]);
        }
        float xt = xr[24];
        acc0[24] = fmaf(wv0, xt, acc0[24]);
        acc1[24] = fmaf(wv1, xt, acc1[24]);
    }

    // combine the two c-halves via smem, then csel==0 writes out.
    // partner threads differ only in bit2 of tid.
    float bb0 = b3[s * OO + o0];
    float bb1 = b3[s * OO + o0 + 1];
    float* outp0 = g_x3 + ((size_t)(n * OO + o0) * KK + s * VV) * TT + t0 + t;
    float* outp1 = outp0 + (size_t)KK * TT;

#pragma unroll 1
    for (int v = 0; v < VV; ++v) {
        partial[tid] = acc0[v];
        __syncthreads();
        if (csel == 0) outp0[v * TT] = bb0 + acc0[v] + partial[tid + 4];
        __syncthreads();
        partial[tid] = acc1[v];
        __syncthreads();
        if (csel == 0) outp1[v * TT] = bb1 + acc1[v] + partial[tid + 4];
        __syncthreads();
    }
}

// ============================================================
// K3b: y[n,o,t,u] = sum_k x3[n,o,k,t] m[n,o,k,u]  (scalar fmaf, proven)
// CTA per (n,o). 64 threads = t. Also produces g_pool[n,o].
// ============================================================
__global__ void __launch_bounds__(64)
k3b_y() {
    int n = blockIdx.x >> 6, o = blockIdx.x & 63;
    int t = threadIdx.x;

    __shared__ float m_s[KK * 28];            // 8.4KB (reused as y stage)
    __shared__ float psum[64];

    for (int i = t; i < SS * VV * VV; i += 64) {
        int s = i / (VV * VV);
        int vu = i % (VV * VV);
        m_s[(s * VV + vu / VV) * 28 + (vu % VV)] =
            g_m[((size_t)(n * SS + s) * OO + o) * (VV * VV) + vu];
    }
    __syncthreads();

    float acc[VV];
#pragma unroll
    for (int u = 0; u < VV; ++u) acc[u] = 0.f;

    const float* xp = g_x3 + (size_t)(n * OO + o) * (KK * TT) + t;

#pragma unroll 5
    for (int k = 0; k < KK; ++k) {
        float xx = __ldg(xp + k * TT);
        const float* mr = m_s + k * 28;
#pragma unroll
        for (int u4 = 0; u4 < 6; ++u4) {
            float4 q = *(const float4*)(mr + u4 * 4);
            acc[u4 * 4 + 0] = fmaf(xx, q.x, acc[u4 * 4 + 0]);
            acc[u4 * 4 + 1] = fmaf(xx, q.y, acc[u4 * 4 + 1]);
            acc[u4 * 4 + 2] = fmaf(xx, q.z, acc[u4 * 4 + 2]);
            acc[u4 * 4 + 3] = fmaf(xx, q.w, acc[u4 * 4 + 3]);
        }
        acc[24] = fmaf(xx, mr[24], acc[24]);
    }

    __syncthreads();
    float* yst = m_s;
    float tsum = 0.f;
#pragma unroll
    for (int u = 0; u < VV; ++u) {
        yst[t * VV + u] = acc[u];
        tsum += acc[u];
    }
    psum[t] = tsum;
    __syncthreads();

    {
        float4* dst = (float4*)(g_y + (size_t)(n * OO + o) * (TT * VV));
        const float4* src = (const float4*)yst;
        for (int i = t; i < TT * VV / 4; i += 64) dst[i] = src[i];
    }
    if (t == 0) {
        float tot = 0.f;
#pragma unroll
        for (int i = 0; i < 64; ++i) tot += psum[i];
        g_pool[n * OO + o] = tot;
    }
}

// ============================================================
// K4: BN + SE -> per-(n,o) affine (pool precomputed by K3b)
// One CTA per n, 64 threads.
// ============================================================
__global__ void __launch_bounds__(64)
k4_se(const float* __restrict__ bn_w, const float* __restrict__ bn_b,
      const float* __restrict__ se_w1, const float* __restrict__ se_b1,
      const float* __restrict__ se_w2, const float* __restrict__ se_b2) {
    int n = blockIdx.x;
    int tid = threadIdx.x;

    __shared__ float pool[OO];
    __shared__ float hbuf[HH];

    float g = bn_w[tid] * rsqrtf(1.0f + 1e-5f);
    pool[tid] = g * (g_pool[n * OO + tid] * (1.0f / (TT * VV))) + bn_b[tid];
    __syncthreads();

    if (tid < HH) {
        float acc = se_b1[tid];
#pragma unroll
        for (int oo2 = 0; oo2 < OO; ++oo2) acc += pool[oo2] * se_w1[tid * OO + oo2];
        hbuf[tid] = fmaxf(acc, 0.f);
    }
    __syncthreads();

    {
        float acc = se_b2[tid];
#pragma unroll
        for (int jj = 0; jj < HH; ++jj) acc += hbuf[jj] * se_w2[tid * HH + jj];
        float se = 1.0f / (1.0f + __expf(-acc));
        g_sea[n * OO + tid] = g * se;
        g_seb[n * OO + tid] = bn_b[tid] * se;
    }
}

// ============================================================
// K5: out = relu(y * sea + seb + x)
// ============================================================
__global__ void k5_final(const float* __restrict__ x, float* __restrict__ out) {
    int i4 = blockIdx.x * 256 + threadIdx.x;
    if (i4 >= NN * OO * TT * VV / 4) return;
    int no = i4 / 400;
    float a = g_sea[no], b = g_seb[no];
    float4 y4 = ((const float4*)g_y)[i4];
    float4 x4 = ((const float4*)x)[i4];
    float4 r;
    r.x = fmaxf(fmaf(y4.x, a, b) + x4.x, 0.f);
    r.y = fmaxf(fmaf(y4.y, a, b) + x4.y, 0.f);
    r.z = fmaxf(fmaf(y4.z, a, b) + x4.z, 0.f);
    r.w = fmaxf(fmaf(y4.w, a, b) + x4.w, 0.f);
    ((float4*)out)[i4] = r;
}

// ============================================================
extern "C" void kernel_launch(void* const* d_in, const int* in_sizes, int n_in,
                              void* d_out, int out_size) {
    const float* x     = (const float*)d_in[0];
    const float* PA    = (const float*)d_in[1];
    const float* alpha = (const float*)d_in[2];
    const float* w1    = (const float*)d_in[3];
    const float* b1    = (const float*)d_in[4];
    const float* w2    = (const float*)d_in[5];
    const float* b2    = (const float*)d_in[6];
    const float* w3    = (const float*)d_in[7];
    const float* b3    = (const float*)d_in[8];
    const float* w4    = (const float*)d_in[9];
    const float* b4    = (const float*)d_in[10];
    const float* bn_w  = (const float*)d_in[11];
    const float* bn_b  = (const float*)d_in[12];
    const float* se_w1 = (const float*)d_in[13];
    const float* se_b1 = (const float*)d_in[14];
    const float* se_w2 = (const float*)d_in[15];
    const float* se_b2 = (const float*)d_in[16];
    float* out = (float*)d_out;

    k1_mean<<<(NN * CC * VV + 255) / 256, 256>>>(x);               // idx 0
    k2_attn<<<NN * SS, 256>>>(PA, alpha, w1, b1, w2, b2, w4, b4);  // idx 1
    k0_dummy<<<1, 32>>>();                                          // idx 2
    k3a_x3<<<NN * SS * (TT / TCH), 256>>>(x, w3, b3);               // idx 3 (captured)
    k3b_y<<<NN * OO, 64>>>();
    k4_se<<<NN, 64>>>(bn_w, bn_b, se_w1, se_b1, se_w2, se_b2);
    k5_final<<<(NN * OO * TT * VV / 4 + 255) / 256, 256>>>(x, out);
}

// round 12
// speedup vs baseline: 1.7842x; 1.7842x over previous
#include <cuda_runtime.h>

#define NN 256
#define CC 64
#define TT 64
#define VV 25
#define SS 3
#define RR 8
#define OO 64
#define HH 16
#define KK 75   // S*V contraction length

// ---- scratch ----
__device__ float g_xm[NN * CC * VV];
__device__ float g_m[NN * SS * OO * VV * VV];            // [n][s][o][v][u]
__device__ float g_x3[(size_t)NN * OO * KK * TT];        // [n][o][k][t]
__device__ float g_y[NN * OO * TT * VV];                 // [n][o][t][u]
__device__ float g_pool[NN * OO];                        // raw sums of y per (n,o)
__device__ float g_sea[NN * OO];
__device__ float g_seb[NN * OO];

// ============================================================
// K0: dummy (keeps k3a at the profiler's captured launch index)
// ============================================================
__global__ void k0_dummy() {}

// ============================================================
// K1: xm[n,c,v] = mean over T
// ============================================================
__global__ void k1_mean(const float* __restrict__ x) {
    int idx = blockIdx.x * 256 + threadIdx.x;
    if (idx >= NN * CC * VV) return;
    int v  = idx % VV;
    int nc = idx / VV;
    const float* p = x + (size_t)nc * (TT * VV) + v;
    float s = 0.f;
#pragma unroll
    for (int t = 0; t < TT; ++t) s += p[t * VV];
    g_xm[idx] = s * (1.0f / TT);
}

// ============================================================
// K2: attention map + softmax. CTA per (n,s), 256 threads.
// ============================================================
__global__ void k2_attn(const float* __restrict__ PA, const float* __restrict__ alpha,
                        const float* __restrict__ w1, const float* __restrict__ b1,
                        const float* __restrict__ w2, const float* __restrict__ b2,
                        const float* __restrict__ w4, const float* __restrict__ b4) {
    int n = blockIdx.x / SS, s = blockIdx.x % SS;
    int tid = threadIdx.x;

    __shared__ float xms[CC * VV];
    __shared__ float x1s[RR * VV];
    __shared__ float x2s[RR * VV];
    __shared__ float atts[RR * VV * VV];

    for (int i = tid; i < CC * VV; i += 256) xms[i] = g_xm[n * CC * VV + i];
    __syncthreads();

    for (int i2 = tid; i2 < 2 * RR * VV; i2 += 256) {
        int which = i2 / (RR * VV);
        int i = i2 % (RR * VV);
        int r = i / VV, u = i % VV;
        const float* w = (which ? w2 : w1) + (s * RR + r) * CC;
        float acc = (which ? b2 : b1)[s * RR + r];
#pragma unroll
        for (int c = 0; c < CC; ++c) acc += w[c] * xms[c * VV + u];
        (which ? x2s : x1s)[i] = acc;
    }
    __syncthreads();

    for (int i = tid; i < RR * VV * VV; i += 256) {
        int r = i / (VV * VV); int rem = i % (VV * VV);
        int u = rem / VV, v = rem % VV;
        atts[i] = tanhf(x1s[r * VV + u] - x2s[r * VV + v]);
    }
    __syncthreads();

    float al = alpha[s];
    for (int pos = tid; pos < OO * VV; pos += 256) {
        int o = pos / VV, v = pos % VV;
        float wr[RR];
#pragma unroll
        for (int r = 0; r < RR; ++r) wr[r] = w4[(s * OO + o) * RR + r];
        float b4v = b4[s * OO + o];
        float col[VV];
        float mx = -1e30f;
#pragma unroll
        for (int u = 0; u < VV; ++u) {
            float acc = b4v;
#pragma unroll
            for (int r = 0; r < RR; ++r) acc += wr[r] * atts[r * VV * VV + u * VV + v];
            float val = al * acc + PA[(s * VV + u) * VV + v] + PA[(s * VV + v) * VV + u];
            col[u] = val;
            mx = fmaxf(mx, val);
        }
        float ssum = 0.f;
#pragma unroll
        for (int u = 0; u < VV; ++u) { col[u] = __expf(col[u] - mx); ssum += col[u]; }
        float inv = 1.0f / ssum;
        float* outp = g_m + (((size_t)(n * SS + s) * OO + o) * VV + v) * VV;
#pragma unroll
        for (int u = 0; u < VV; ++u) outp[u] = col[u] * inv;
    }
}

// ============================================================
// K3a: x3[n,o,s*25+v,t] = b3[s,o] + sum_c w3[s,o,c] x[n,c,t,v]
// CTA = (n, s, t-chunk of 8). 256 threads = (o-pair:32, t:8).
// R8 inner loop exactly; x staged in 2 c-halves into a 28.7KB buffer
// (total smem 45.3KB) -> 3 CTAs/SM (launch_bounds(256,3), regs<=85).
// Accumulators live across both halves; no combine logic.
// ============================================================
#define TCH 8
#define XSP 28
#define CSP 32
__global__ void __launch_bounds__(256, 3)
k3a_x3(const float* __restrict__ x, const float* __restrict__ w3,
       const float* __restrict__ b3) {
    int bid = blockIdx.x;
    int n = bid / (SS * (TT / TCH));
    int rem = bid % (SS * (TT / TCH));
    int s = rem / (TT / TCH);
    int t0 = (rem % (TT / TCH)) * TCH;
    int tid = threadIdx.x;
    int o0 = (tid >> 3) * 2;
    int t = tid & 7;

    __shared__ float w3s[OO * 65];            // 16.6KB, conflict-free
    __shared__ float x_s[CSP * TCH * XSP];    // 28.7KB (one c-half)

    for (int i = tid; i < OO * CC; i += 256) {
        int oo2 = i >> 6, c = i & 63;
        w3s[oo2 * 65 + c] = w3[s * OO * CC + i];
    }

    float acc0[VV], acc1[VV];
    float bb0 = b3[s * OO + o0];
    float bb1 = b3[s * OO + o0 + 1];
#pragma unroll
    for (int v = 0; v < VV; ++v) { acc0[v] = bb0; acc1[v] = bb1; }

#pragma unroll 1
    for (int cs = 0; cs < 2; ++cs) {
        __syncthreads();
        for (int j = tid; j < CSP * TCH * VV; j += 256) {
            int c = j / (TCH * VV);
            int tv = j % (TCH * VV);
            int tl = tv / VV, v = tv % VV;
            x_s[c * (TCH * XSP) + tl * XSP + v] =
                x[((size_t)(n * CC + cs * CSP + c) * TT + (t0 + tl)) * VV + v];
        }
        __syncthreads();

#pragma unroll 4
        for (int ci = 0; ci < CSP; ++ci) {
            int c = cs * CSP + ci;
            float wv0 = w3s[o0 * 65 + c];
            float wv1 = w3s[(o0 + 1) * 65 + c];
            const float* xr = x_s + ci * (TCH * XSP) + t * XSP;
#pragma unroll
            for (int v4 = 0; v4 < 6; ++v4) {
                float4 q = *(const float4*)(xr + v4 * 4);
                acc0[v4 * 4 + 0] = fmaf(wv0, q.x, acc0[v4 * 4 + 0]);
                acc0[v4 * 4 + 1] = fmaf(wv0, q.y, acc0[v4 * 4 + 1]);
                acc0[v4 * 4 + 2] = fmaf(wv0, q.z, acc0[v4 * 4 + 2]);
                acc0[v4 * 4 + 3] = fmaf(wv0, q.w, acc0[v4 * 4 + 3]);
                acc1[v4 * 4 + 0] = fmaf(wv1, q.x, acc1[v4 * 4 + 0]);
                acc1[v4 * 4 + 1] = fmaf(wv1, q.y, acc1[v4 * 4 + 1]);
                acc1[v4 * 4 + 2] = fmaf(wv1, q.z, acc1[v4 * 4 + 2]);
                acc1[v4 * 4 + 3] = fmaf(wv1, q.w, acc1[v4 * 4 + 3]);
            }
            float xt = xr[24];
            acc0[24] = fmaf(wv0, xt, acc0[24]);
            acc1[24] = fmaf(wv1, xt, acc1[24]);
        }
    }

    float* outp0 = g_x3 + ((size_t)(n * OO + o0) * KK + s * VV) * TT + t0 + t;
    float* outp1 = outp0 + (size_t)KK * TT;
#pragma unroll
    for (int v = 0; v < VV; ++v) {
        outp0[v * TT] = acc0[v];
        outp1[v * TT] = acc1[v];
    }
}

// ============================================================
// K3b: y[n,o,t,u] = sum_k x3[n,o,k,t] m[n,o,k,u]  (scalar fmaf, proven)
// CTA per (n,o). 64 threads = t. Also produces g_pool[n,o].
// ============================================================
__global__ void __launch_bounds__(64)
k3b_y() {
    int n = blockIdx.x >> 6, o = blockIdx.x & 63;
    int t = threadIdx.x;

    __shared__ float m_s[KK * 28];            // 8.4KB (reused as y stage)
    __shared__ float psum[64];

    for (int i = t; i < SS * VV * VV; i += 64) {
        int s = i / (VV * VV);
        int vu = i % (VV * VV);
        m_s[(s * VV + vu / VV) * 28 + (vu % VV)] =
            g_m[((size_t)(n * SS + s) * OO + o) * (VV * VV) + vu];
    }
    __syncthreads();

    float acc[VV];
#pragma unroll
    for (int u = 0; u < VV; ++u) acc[u] = 0.f;

    const float* xp = g_x3 + (size_t)(n * OO + o) * (KK * TT) + t;

#pragma unroll 5
    for (int k = 0; k < KK; ++k) {
        float xx = __ldg(xp + k * TT);
        const float* mr = m_s + k * 28;
#pragma unroll
        for (int u4 = 0; u4 < 6; ++u4) {
            float4 q = *(const float4*)(mr + u4 * 4);
            acc[u4 * 4 + 0] = fmaf(xx, q.x, acc[u4 * 4 + 0]);
            acc[u4 * 4 + 1] = fmaf(xx, q.y, acc[u4 * 4 + 1]);
            acc[u4 * 4 + 2] = fmaf(xx, q.z, acc[u4 * 4 + 2]);
            acc[u4 * 4 + 3] = fmaf(xx, q.w, acc[u4 * 4 + 3]);
        }
        acc[24] = fmaf(xx, mr[24], acc[24]);
    }

    __syncthreads();
    float* yst = m_s;
    float tsum = 0.f;
#pragma unroll
    for (int u = 0; u < VV; ++u) {
        yst[t * VV + u] = acc[u];
        tsum += acc[u];
    }
    psum[t] = tsum;
    __syncthreads();

    {
        float4* dst = (float4*)(g_y + (size_t)(n * OO + o) * (TT * VV));
        const float4* src = (const float4*)yst;
        for (int i = t; i < TT * VV / 4; i += 64) dst[i] = src[i];
    }
    if (t == 0) {
        float tot = 0.f;
#pragma unroll
        for (int i = 0; i < 64; ++i) tot += psum[i];
        g_pool[n * OO + o] = tot;
    }
}

// ============================================================
// K4: BN + SE -> per-(n,o) affine (pool precomputed by K3b)
// One CTA per n, 64 threads.
// ============================================================
__global__ void __launch_bounds__(64)
k4_se(const float* __restrict__ bn_w, const float* __restrict__ bn_b,
      const float* __restrict__ se_w1, const float* __restrict__ se_b1,
      const float* __restrict__ se_w2, const float* __restrict__ se_b2) {
    int n = blockIdx.x;
    int tid = threadIdx.x;

    __shared__ float pool[OO];
    __shared__ float hbuf[HH];

    float g = bn_w[tid] * rsqrtf(1.0f + 1e-5f);
    pool[tid] = g * (g_pool[n * OO + tid] * (1.0f / (TT * VV))) + bn_b[tid];
    __syncthreads();

    if (tid < HH) {
        float acc = se_b1[tid];
#pragma unroll
        for (int oo2 = 0; oo2 < OO; ++oo2) acc += pool[oo2] * se_w1[tid * OO + oo2];
        hbuf[tid] = fmaxf(acc, 0.f);
    }
    __syncthreads();

    {
        float acc = se_b2[tid];
#pragma unroll
        for (int jj = 0; jj < HH; ++jj) acc += hbuf[jj] * se_w2[tid * HH + jj];
        float se = 1.0f / (1.0f + __expf(-acc));
        g_sea[n * OO + tid] = g * se;
        g_seb[n * OO + tid] = bn_b[tid] * se;
    }
}

// ============================================================
// K5: out = relu(y * sea + seb + x)
// ============================================================
__global__ void k5_final(const float* __restrict__ x, float* __restrict__ out) {
    int i4 = blockIdx.x * 256 + threadIdx.x;
    if (i4 >= NN * OO * TT * VV / 4) return;
    int no = i4 / 400;
    float a = g_sea[no], b = g_seb[no];
    float4 y4 = ((const float4*)g_y)[i4];
    float4 x4 = ((const float4*)x)[i4];
    float4 r;
    r.x = fmaxf(fmaf(y4.x, a, b) + x4.x, 0.f);
    r.y = fmaxf(fmaf(y4.y, a, b) + x4.y, 0.f);
    r.z = fmaxf(fmaf(y4.z, a, b) + x4.z, 0.f);
    r.w = fmaxf(fmaf(y4.w, a, b) + x4.w, 0.f);
    ((float4*)out)[i4] = r;
}

// ============================================================
extern "C" void kernel_launch(void* const* d_in, const int* in_sizes, int n_in,
                              void* d_out, int out_size) {
    const float* x     = (const float*)d_in[0];
    const float* PA    = (const float*)d_in[1];
    const float* alpha = (const float*)d_in[2];
    const float* w1    = (const float*)d_in[3];
    const float* b1    = (const float*)d_in[4];
    const float* w2    = (const float*)d_in[5];
    const float* b2    = (const float*)d_in[6];
    const float* w3    = (const float*)d_in[7];
    const float* b3    = (const float*)d_in[8];
    const float* w4    = (const float*)d_in[9];
    const float* b4    = (const float*)d_in[10];
    const float* bn_w  = (const float*)d_in[11];
    const float* bn_b  = (const float*)d_in[12];
    const float* se_w1 = (const float*)d_in[13];
    const float* se_b1 = (const float*)d_in[14];
    const float* se_w2 = (const float*)d_in[15];
    const float* se_b2 = (const float*)d_in[16];
    float* out = (float*)d_out;

    k1_mean<<<(NN * CC * VV + 255) / 256, 256>>>(x);               // idx 0
    k2_attn<<<NN * SS, 256>>>(PA, alpha, w1, b1, w2, b2, w4, b4);  // idx 1
    k0_dummy<<<1, 32>>>();                                          // idx 2
    k3a_x3<<<NN * SS * (TT / TCH), 256>>>(x, w3, b3);               // idx 3 (captured)
    k3b_y<<<NN * OO, 64>>>();
    k4_se<<<NN, 64>>>(bn_w, bn_b, se_w1, se_b1, se_w2, se_b2);
    k5_final<<<(NN * OO * TT * VV / 4 + 255) / 256, 256>>>(x, out);
}

// round 14
// speedup vs baseline: 2.1501x; 1.2051x over previous
#include <cuda_runtime.h>
#include <cuda_bf16.h>
#include <cstdint>

#define NN 256
#define CC 64
#define TT 64
#define VV 25
#define SS 3
#define RR 8
#define OO 64
#define HH 16
#define KK 75   // S*V contraction length
#define NVT 13  // v-pair tiles per (n,s)

// ---- scratch ----
__device__ float g_xm[NN * CC * VV];
__device__ float g_m[NN * SS * OO * VV * VV];            // [n][s][o][v][u]
__device__ float g_x3[(size_t)NN * OO * KK * TT];        // [n][o][k][t]
__device__ float g_y[NN * OO * TT * VV];                 // [n][o][t][u]
__device__ float g_pool[NN * OO];
__device__ float g_sea[NN * OO];
__device__ float g_seb[NN * OO];
// transposed bf16 split of x: [n][tv=1600][c=64]
__device__ __nv_bfloat16 g_xt_hi[(size_t)NN * TT * VV * CC];
__device__ __nv_bfloat16 g_xt_lo[(size_t)NN * TT * VV * CC];

#define SMEM_SWIZZLE_128B(off) ((off) ^ (((off) >> 3) & 0x70))

__device__ __forceinline__ uint32_t smem_to_u32(const void* p) {
    uint32_t a;
    asm("{ .reg .u64 t; cvta.to.shared.u64 t, %1; cvt.u32.u64 %0, t; }"
        : "=r"(a) : "l"(p));
    return a;
}
__device__ __forceinline__ void ldm_x4(uint32_t* r, uint32_t addr) {
    asm volatile("ldmatrix.sync.aligned.m8n8.x4.shared.b16 {%0,%1,%2,%3}, [%4];"
                 : "=r"(r[0]), "=r"(r[1]), "=r"(r[2]), "=r"(r[3]) : "r"(addr));
}
__device__ __forceinline__ void ldm_x2(uint32_t* r, uint32_t addr) {
    asm volatile("ldmatrix.sync.aligned.m8n8.x2.shared.b16 {%0,%1}, [%2];"
                 : "=r"(r[0]), "=r"(r[1]) : "r"(addr));
}
__device__ __forceinline__ void mma16816(float* d, const uint32_t* a, const uint32_t* b) {
    asm volatile("mma.sync.aligned.m16n8k16.row.col.f32.bf16.bf16.f32 "
                 "{%0,%1,%2,%3}, {%4,%5,%6,%7}, {%8,%9}, {%0,%1,%2,%3};"
                 : "+f"(d[0]), "+f"(d[1]), "+f"(d[2]), "+f"(d[3])
                 : "r"(a[0]), "r"(a[1]), "r"(a[2]), "r"(a[3]),
                   "r"(b[0]), "r"(b[1]));
}
__device__ __forceinline__ void bf16_split(float f, unsigned short& h, unsigned short& l) {
    __nv_bfloat16 hb = __float2bfloat16(f);
    float r = f - __bfloat162float(hb);
    __nv_bfloat16 lb = __float2bfloat16(r);
    h = __bfloat16_as_ushort(hb);
    l = __bfloat16_as_ushort(lb);
}

// ============================================================
// K1: xm[n,c,v] = mean over T
// ============================================================
__global__ void k1_mean(const float* __restrict__ x) {
    int idx = blockIdx.x * 256 + threadIdx.x;
    if (idx >= NN * CC * VV) return;
    int v  = idx % VV;
    int nc = idx / VV;
    const float* p = x + (size_t)nc * (TT * VV) + v;
    float s = 0.f;
#pragma unroll
    for (int t = 0; t < TT; ++t) s += p[t * VV];
    g_xm[idx] = s * (1.0f / TT);
}

// ============================================================
// K2: attention map + softmax. CTA per (n,s), 256 threads.
// ============================================================
__global__ void k2_attn(const float* __restrict__ PA, const float* __restrict__ alpha,
                        const float* __restrict__ w1, const float* __restrict__ b1,
                        const float* __restrict__ w2, const float* __restrict__ b2,
                        const float* __restrict__ w4, const float* __restrict__ b4) {
    int n = blockIdx.x / SS, s = blockIdx.x % SS;
    int tid = threadIdx.x;

    __shared__ float xms[CC * VV];
    __shared__ float x1s[RR * VV];
    __shared__ float x2s[RR * VV];
    __shared__ float atts[RR * VV * VV];

    for (int i = tid; i < CC * VV; i += 256) xms[i] = g_xm[n * CC * VV + i];
    __syncthreads();

    for (int i2 = tid; i2 < 2 * RR * VV; i2 += 256) {
        int which = i2 / (RR * VV);
        int i = i2 % (RR * VV);
        int r = i / VV, u = i % VV;
        const float* w = (which ? w2 : w1) + (s * RR + r) * CC;
        float acc = (which ? b2 : b1)[s * RR + r];
#pragma unroll
        for (int c = 0; c < CC; ++c) acc += w[c] * xms[c * VV + u];
        (which ? x2s : x1s)[i] = acc;
    }
    __syncthreads();

    for (int i = tid; i < RR * VV * VV; i += 256) {
        int r = i / (VV * VV); int rem = i % (VV * VV);
        int u = rem / VV, v = rem % VV;
        atts[i] = tanhf(x1s[r * VV + u] - x2s[r * VV + v]);
    }
    __syncthreads();

    float al = alpha[s];
    for (int pos = tid; pos < OO * VV; pos += 256) {
        int o = pos / VV, v = pos % VV;
        float wr[RR];
#pragma unroll
        for (int r = 0; r < RR; ++r) wr[r] = w4[(s * OO + o) * RR + r];
        float b4v = b4[s * OO + o];
        float col[VV];
        float mx = -1e30f;
#pragma unroll
        for (int u = 0; u < VV; ++u) {
            float acc = b4v;
#pragma unroll
            for (int r = 0; r < RR; ++r) acc += wr[r] * atts[r * VV * VV + u * VV + v];
            float val = al * acc + PA[(s * VV + u) * VV + v] + PA[(s * VV + v) * VV + u];
            col[u] = val;
            mx = fmaxf(mx, val);
        }
        float ssum = 0.f;
#pragma unroll
        for (int u = 0; u < VV; ++u) { col[u] = __expf(col[u] - mx); ssum += col[u]; }
        float inv = 1.0f / ssum;
        float* outp = g_m + (((size_t)(n * SS + s) * OO + o) * VV + v) * VV;
#pragma unroll
        for (int u = 0; u < VV; ++u) outp[u] = col[u] * inv;
    }
}

// ============================================================
// K_xt: transpose + bf16-split x -> g_xt_hi/lo [n][tv][c]
// ============================================================
__global__ void __launch_bounds__(256)
k_xt(const float* __restrict__ x) {
    __shared__ float sm[CC * 129];
    int n = blockIdx.x / NVT;
    int ch = blockIdx.x % NVT;
    int tv0 = ch * 128;
    int tid = threadIdx.x;
    int lim = TT * VV - tv0; if (lim > 128) lim = 128;

    for (int i = tid; i < CC * 128; i += 256) {
        int c = i >> 7, tvl = i & 127;
        sm[c * 129 + tvl] = (tvl < lim)
            ? x[((size_t)n * CC + c) * (TT * VV) + tv0 + tvl] : 0.f;
    }
    __syncthreads();

    for (int i = tid; i < 128 * 32; i += 256) {
        int tvl = i >> 5, cp = i & 31;
        if (tvl >= lim) continue;
        float f0 = sm[(2 * cp) * 129 + tvl];
        float f1 = sm[(2 * cp + 1) * 129 + tvl];
        unsigned short h0, l0, h1, l1;
        bf16_split(f0, h0, l0);
        bf16_split(f1, h1, l1);
        size_t base = ((size_t)n * (TT * VV) + tv0 + tvl) * CC + 2 * cp;
        *(uint32_t*)((__nv_bfloat16*)g_xt_hi + base) = ((uint32_t)h1 << 16) | h0;
        *(uint32_t*)((__nv_bfloat16*)g_xt_lo + base) = ((uint32_t)l1 << 16) | l0;
    }
}

// ============================================================
// K3a-mma: warp-level bf16 split-precision GEMM (HMMA).
// CTA = (n, s, v-pair tile). 128 threads / 4 warps.
// D[row=(vloc,t):128, o:64] = X_T[row,c] · W3[o,c]^T via 3 passes.
// ============================================================
#define MA_A_HI 0
#define MA_A_LO 16384
#define MA_B_HI 32768
#define MA_B_LO 40960

__global__ void __launch_bounds__(128)
k3a_mma(const float* __restrict__ w3, const float* __restrict__ b3) {
    __shared__ __align__(16) char sm[49152];
    uint32_t sb = smem_to_u32(sm);
    int tid = threadIdx.x;
    int wid = tid >> 5, lane = tid & 31;
    int bid = blockIdx.x;
    int n = bid / (SS * NVT);
    int rem = bid % (SS * NVT);
    int s = rem / NVT;
    int v0 = (rem % NVT) * 2;

    // stage B (w3[s][o][c] -> bf16 hi/lo, swizzled 128B rows)
    for (int i = tid; i < OO * 32; i += 128) {
        int o = i >> 5, cp = i & 31;
        const float* wp = w3 + (size_t)(s * OO + o) * CC + 2 * cp;
        unsigned short h0, l0, h1, l1;
        bf16_split(wp[0], h0, l0);
        bf16_split(wp[1], h1, l1);
        uint32_t sw = SMEM_SWIZZLE_128B(o * 128 + cp * 4);
        *(uint32_t*)(sm + MA_B_HI + sw) = ((uint32_t)h1 << 16) | h0;
        *(uint32_t*)(sm + MA_B_LO + sw) = ((uint32_t)l1 << 16) | l0;
    }
    // stage A (rows = (vloc,t), cols c) from pre-split g_xt
    for (int i = tid; i < 128 * 32; i += 128) {
        int row = i >> 5, cp = i & 31;
        int vloc = row >> 6, t = row & 63;
        uint32_t hp = 0, lp = 0;
        if (v0 + vloc < VV) {
            size_t base = ((size_t)n * (TT * VV) + t * VV + v0 + vloc) * CC + 2 * cp;
            hp = *(const uint32_t*)((const __nv_bfloat16*)g_xt_hi + base);
            lp = *(const uint32_t*)((const __nv_bfloat16*)g_xt_lo + base);
        }
        uint32_t sw = SMEM_SWIZZLE_128B(row * 128 + cp * 4);
        *(uint32_t*)(sm + MA_A_HI + sw) = hp;
        *(uint32_t*)(sm + MA_A_LO + sw) = lp;
    }
    __syncthreads();

    float d[2][8][4];
#pragma unroll
    for (int mt = 0; mt < 2; ++mt)
#pragma unroll
        for (int nt = 0; nt < 8; ++nt)
#pragma unroll
            for (int r = 0; r < 4; ++r) d[mt][nt][r] = 0.f;

    // ldmatrix lane addressing
    // A x4: sub = lane>>3 ; row_in = lane&7 ; row = (sub&1)*8 + row_in ; chunk = sub>>1
    int a_row = ((lane >> 3) & 1) * 8 + (lane & 7);
    int a_chunk = lane >> 4;
    // B x2 (lanes 0-15): row = lane&7 ; chunk = (lane>>3)&1
    int b_rowl = (lane & 15) & 7;
    int b_chunk = ((lane & 15) >> 3) & 1;

#pragma unroll
    for (int pass = 0; pass < 3; ++pass) {
        uint32_t Abase = sb + ((pass == 2) ? MA_A_LO : MA_A_HI);
        uint32_t Bbase = sb + ((pass == 1) ? MA_B_LO : MA_B_HI);
#pragma unroll
        for (int ks = 0; ks < 4; ++ks) {
            uint32_t a[2][4];
#pragma unroll
            for (int mt = 0; mt < 2; ++mt) {
                int row = wid * 32 + mt * 16 + a_row;
                ldm_x4(a[mt], Abase + SMEM_SWIZZLE_128B(row * 128 + ks * 32 + a_chunk * 16));
            }
#pragma unroll
            for (int nt = 0; nt < 8; ++nt) {
                uint32_t b[2];
                int brow = nt * 8 + b_rowl;
                ldm_x2(b, Bbase + SMEM_SWIZZLE_128B(brow * 128 + ks * 32 + b_chunk * 16));
                mma16816(d[0][nt], a[0], b);
                mma16816(d[1][nt], a[1], b);
            }
        }
    }

    // stage D through smem (rows 128 x 65 floats, conflict-free) for coalesced out
    __syncthreads();
    float* ds = (float*)sm;
#pragma unroll
    for (int mt = 0; mt < 2; ++mt)
#pragma unroll
        for (int nt = 0; nt < 8; ++nt)
#pragma unroll
            for (int r = 0; r < 4; ++r) {
                int row = wid * 32 + mt * 16 + (lane >> 2) + (r >> 1) * 8;
                int col = nt * 8 + 2 * (lane & 3) + (r & 1);
                ds[row * 65 + col] = d[mt][nt][r];
            }
    __syncthreads();

    // out: thread tid handles row=tid over all o (coalesced in t across lanes)
    int vloc = tid >> 6, t = tid & 63;
    if (v0 + vloc < VV) {
        size_t base = ((size_t)(n * OO) * KK + s * VV + v0 + vloc) * TT + t;
#pragma unroll 8
        for (int o = 0; o < OO; ++o)
            g_x3[base + (size_t)o * (KK * TT)] =
                ds[tid * 65 + o] + __ldg(&b3[s * OO + o]);
    }
}

// ============================================================
// K3b: y[n,o,t,u] = sum_k x3[n,o,k,t] m[n,o,k,u]  (proven)
// ============================================================
__global__ void __launch_bounds__(64)
k3b_y() {
    int n = blockIdx.x >> 6, o = blockIdx.x & 63;
    int t = threadIdx.x;

    __shared__ float m_s[KK * 28];
    __shared__ float psum[64];

    for (int i = t; i < SS * VV * VV; i += 64) {
        int s = i / (VV * VV);
        int vu = i % (VV * VV);
        m_s[(s * VV + vu / VV) * 28 + (vu % VV)] =
            g_m[((size_t)(n * SS + s) * OO + o) * (VV * VV) + vu];
    }
    __syncthreads();

    float acc[VV];
#pragma unroll
    for (int u = 0; u < VV; ++u) acc[u] = 0.f;

    const float* xp = g_x3 + (size_t)(n * OO + o) * (KK * TT) + t;

#pragma unroll 5
    for (int k = 0; k < KK; ++k) {
        float xx = __ldg(xp + k * TT);
        const float* mr = m_s + k * 28;
#pragma unroll
        for (int u4 = 0; u4 < 6; ++u4) {
            float4 q = *(const float4*)(mr + u4 * 4);
            acc[u4 * 4 + 0] = fmaf(xx, q.x, acc[u4 * 4 + 0]);
            acc[u4 * 4 + 1] = fmaf(xx, q.y, acc[u4 * 4 + 1]);
            acc[u4 * 4 + 2] = fmaf(xx, q.z, acc[u4 * 4 + 2]);
            acc[u4 * 4 + 3] = fmaf(xx, q.w, acc[u4 * 4 + 3]);
        }
        acc[24] = fmaf(xx, mr[24], acc[24]);
    }

    __syncthreads();
    float* yst = m_s;
    float tsum = 0.f;
#pragma unroll
    for (int u = 0; u < VV; ++u) {
        yst[t * VV + u] = acc[u];
        tsum += acc[u];
    }
    psum[t] = tsum;
    __syncthreads();

    {
        float4* dst = (float4*)(g_y + (size_t)(n * OO + o) * (TT * VV));
        const float4* src = (const float4*)yst;
        for (int i = t; i < TT * VV / 4; i += 64) dst[i] = src[i];
    }
    if (t == 0) {
        float tot = 0.f;
#pragma unroll
        for (int i = 0; i < 64; ++i) tot += psum[i];
        g_pool[n * OO + o] = tot;
    }
}

// ============================================================
// K4: BN + SE -> per-(n,o) affine (pool precomputed by K3b)
// ============================================================
__global__ void __launch_bounds__(64)
k4_se(const float* __restrict__ bn_w, const float* __restrict__ bn_b,
      const float* __restrict__ se_w1, const float* __restrict__ se_b1,
      const float* __restrict__ se_w2, const float* __restrict__ se_b2) {
    int n = blockIdx.x;
    int tid = threadIdx.x;

    __shared__ float pool[OO];
    __shared__ float hbuf[HH];

    float g = bn_w[tid] * rsqrtf(1.0f + 1e-5f);
    pool[tid] = g * (g_pool[n * OO + tid] * (1.0f / (TT * VV))) + bn_b[tid];
    __syncthreads();

    if (tid < HH) {
        float acc = se_b1[tid];
#pragma unroll
        for (int oo2 = 0; oo2 < OO; ++oo2) acc += pool[oo2] * se_w1[tid * OO + oo2];
        hbuf[tid] = fmaxf(acc, 0.f);
    }
    __syncthreads();

    {
        float acc = se_b2[tid];
#pragma unroll
        for (int jj = 0; jj < HH; ++jj) acc += hbuf[jj] * se_w2[tid * HH + jj];
        float se = 1.0f / (1.0f + __expf(-acc));
        g_sea[n * OO + tid] = g * se;
        g_seb[n * OO + tid] = bn_b[tid] * se;
    }
}

// ============================================================
// K5: out = relu(y * sea + seb + x)
// ============================================================
__global__ void k5_final(const float* __restrict__ x, float* __restrict__ out) {
    int i4 = blockIdx.x * 256 + threadIdx.x;
    if (i4 >= NN * OO * TT * VV / 4) return;
    int no = i4 / 400;
    float a = g_sea[no], b = g_seb[no];
    float4 y4 = ((const float4*)g_y)[i4];
    float4 x4 = ((const float4*)x)[i4];
    float4 r;
    r.x = fmaxf(fmaf(y4.x, a, b) + x4.x, 0.f);
    r.y = fmaxf(fmaf(y4.y, a, b) + x4.y, 0.f);
    r.z = fmaxf(fmaf(y4.z, a, b) + x4.z, 0.f);
    r.w = fmaxf(fmaf(y4.w, a, b) + x4.w, 0.f);
    ((float4*)out)[i4] = r;
}

// ============================================================
extern "C" void kernel_launch(void* const* d_in, const int* in_sizes, int n_in,
                              void* d_out, int out_size) {
    const float* x     = (const float*)d_in[0];
    const float* PA    = (const float*)d_in[1];
    const float* alpha = (const float*)d_in[2];
    const float* w1    = (const float*)d_in[3];
    const float* b1    = (const float*)d_in[4];
    const float* w2    = (const float*)d_in[5];
    const float* b2    = (const float*)d_in[6];
    const float* w3    = (const float*)d_in[7];
    const float* b3    = (const float*)d_in[8];
    const float* w4    = (const float*)d_in[9];
    const float* b4    = (const float*)d_in[10];
    const float* bn_w  = (const float*)d_in[11];
    const float* bn_b  = (const float*)d_in[12];
    const float* se_w1 = (const float*)d_in[13];
    const float* se_b1 = (const float*)d_in[14];
    const float* se_w2 = (const float*)d_in[15];
    const float* se_b2 = (const float*)d_in[16];
    float* out = (float*)d_out;

    k1_mean<<<(NN * CC * VV + 255) / 256, 256>>>(x);               // idx 0
    k2_attn<<<NN * SS, 256>>>(PA, alpha, w1, b1, w2, b2, w4, b4);  // idx 1
    k_xt<<<NN * NVT, 256>>>(x);                                     // idx 2
    k3a_mma<<<NN * SS * NVT, 128>>>(w3, b3);                        // idx 3 (captured)
    k3b_y<<<NN * OO, 64>>>();
    k4_se<<<NN, 64>>>(bn_w, bn_b, se_w1, se_b1, se_w2, se_b2);
    k5_final<<<(NN * OO * TT * VV / 4 + 255) / 256, 256>>>(x, out);
}